// round 4
// baseline (speedup 1.0000x reference)
#include <cuda_runtime.h>
#include <cuda_bf16.h>

// Problem constants
#define T_DIM 32768
#define D_DIM 1024
#define L_CHUNK 128
#define C_CHUNKS (T_DIM / L_CHUNK)   // 256

#define ETA_MU_F 0.01f
#define A_MU_F   0.99f
#define ETA_V_F  0.02f
#define CV_F     0.98f

// Per-(chunk, column) aggregates. Static device scratch (no allocation allowed).
__device__ float g_cmu[C_CHUNKS * D_DIM];    // chunk-local zero-state EWMA end value
__device__ float g_P[C_CHUNKS * D_DIM];      // var quadratic: constant term
__device__ float g_Q[C_CHUNKS * D_DIM];      // var quadratic: linear coefficient
__device__ float g_sum[C_CHUNKS * D_DIM];    // chunk sum of x
__device__ float g_ss[C_CHUNKS * D_DIM];     // chunk sum of x^2
__device__ float g_mus[C_CHUNKS * D_DIM];    // composed mu at chunk entry
__device__ float g_vas[C_CHUNKS * D_DIM];    // composed var at chunk entry

// ---------------------------------------------------------------------------
// Pass 1: one vectorized read of x. Per (chunk c, column d):
//   sum, sumsq                       -> for mu0 / std0
//   m   (zero-state chunk EWMA)      -> c_mu aggregate
//   Pa = sum cv^{L-1-i} u_i^2,  Qa = sum cv^{L-1-i} u_i a^{i+1},  u_i = x_i - m_i
// Each thread owns 4 adjacent columns (float4).
// ---------------------------------------------------------------------------
__global__ __launch_bounds__(128) void p1_kernel(const float4* __restrict__ x4) {
    const int d4 = blockIdx.x * blockDim.x + threadIdx.x;   // 0..255 (column group)
    const int c  = blockIdx.y;
    const float4* xp = x4 + (size_t)c * L_CHUNK * (D_DIM / 4) + d4;

    float m[4]   = {0.f, 0.f, 0.f, 0.f};
    float sum[4] = {0.f, 0.f, 0.f, 0.f};
    float ss[4]  = {0.f, 0.f, 0.f, 0.f};
    float Pa[4]  = {0.f, 0.f, 0.f, 0.f};
    float Qa[4]  = {0.f, 0.f, 0.f, 0.f};
    float g = A_MU_F;  // a^{i+1}

    #pragma unroll 4
    for (int i = 0; i < L_CHUNK; i++) {
        float4 xv4 = xp[(size_t)i * (D_DIM / 4)];
        float xv[4] = {xv4.x, xv4.y, xv4.z, xv4.w};
        #pragma unroll
        for (int k = 0; k < 4; k++) {
            float v = xv[k];
            sum[k] += v;
            ss[k] = fmaf(v, v, ss[k]);
            m[k] = fmaf(ETA_MU_F, v - m[k], m[k]);   // reference rounding form
            float u = v - m[k];
            Pa[k] = fmaf(CV_F, Pa[k], u * u);
            Qa[k] = fmaf(CV_F, Qa[k], u * g);
        }
        g *= A_MU_F;
    }
    #pragma unroll
    for (int k = 0; k < 4; k++) {
        const int idx = c * D_DIM + d4 * 4 + k;
        g_cmu[idx] = m[k];
        g_P[idx]   = ETA_V_F * Pa[k];
        g_Q[idx]   = ETA_V_F * Qa[k];
        g_sum[idx] = sum[k];
        g_ss[idx]  = ss[k];
    }
}

// ---------------------------------------------------------------------------
// Pass 2: tiny. One thread per column.
//   mu0 = mean, var0 = unbiased std (stored into the 'var' slot, as reference).
//   Sequentially compose 256 chunk-entry states:
//     mu_next  = a^L  * mu  + c_mu[c]
//     var_next = cv^L * var + (P[c] - 2 Q[c] mu + R mu^2)
// ---------------------------------------------------------------------------
__global__ __launch_bounds__(256) void p2_kernel() {
    const int d = blockIdx.x * blockDim.x + threadIdx.x;
    if (d >= D_DIM) return;

    double tsum = 0.0, tss = 0.0;
    #pragma unroll 8
    for (int c = 0; c < C_CHUNKS; c++) {
        tsum += (double)g_sum[c * D_DIM + d];
        tss  += (double)g_ss[c * D_DIM + d];
    }
    const double Td = (double)T_DIM;
    float mu0  = (float)(tsum / Td);
    float var0 = (float)sqrt((tss - tsum * tsum / Td) / (Td - 1.0));

    // Constants in double: a^L, cv^L, R = sum_i ev * cv^{L-1-i} * a^{2(i+1)}
    double Am = 1.0, Av = 1.0, R = 0.0, g2 = 0.9801;  // a^2
    for (int i = 0; i < L_CHUNK; i++) {
        Am *= 0.99;
        Av *= 0.98;
        R = R * 0.98 + 0.02 * g2;
        g2 *= 0.9801;
    }
    const float AmL = (float)Am;
    const float AvL = (float)Av;
    const float Rc  = (float)R;

    float s = mu0, v = var0;
    #pragma unroll 4
    for (int c = 0; c < C_CHUNKS; c++) {
        const int idx = c * D_DIM + d;
        g_mus[idx] = s;
        g_vas[idx] = v;
        float cmu = g_cmu[idx];
        float Pv  = g_P[idx];
        float Qv  = g_Q[idx];
        float cvar = fmaf(s, fmaf(s, Rc, -2.0f * Qv), Pv);  // P - 2Qs + Rs^2
        v = fmaf(AvL, v, cvar);
        s = fmaf(AmL, s, cmu);
    }
}

// ---------------------------------------------------------------------------
// Pass 5: second vectorized read of x. Replay each chunk serially with the
// exact fp32 arithmetic of the reference; write norm, mu, var as float4.
// ---------------------------------------------------------------------------
__global__ __launch_bounds__(128) void p5_kernel(const float4* __restrict__ x4,
                                                 float4* __restrict__ out4) {
    float4* __restrict__ norm = out4;                                  // [T, D/4]
    float4* __restrict__ info = out4 + (size_t)T_DIM * (D_DIM / 4);    // [T, 2D/4]

    const int d4 = blockIdx.x * blockDim.x + threadIdx.x;  // 0..255
    const int c  = blockIdx.y;
    const int d0 = d4 * 4;

    float mu[4], var[4];
    #pragma unroll
    for (int k = 0; k < 4; k++) {
        mu[k]  = g_mus[c * D_DIM + d0 + k];
        var[k] = g_vas[c * D_DIM + d0 + k];
    }

    const size_t tbase = (size_t)c * L_CHUNK;
    #pragma unroll 2
    for (int i = 0; i < L_CHUNK; i++) {
        const size_t t = tbase + i;
        float4 xv4 = x4[t * (D_DIM / 4) + d4];
        float xv[4] = {xv4.x, xv4.y, xv4.z, xv4.w};
        float nv[4];
        #pragma unroll
        for (int k = 0; k < 4; k++) {
            mu[k] = fmaf(ETA_MU_F, xv[k] - mu[k], mu[k]);          // mu += eta*(x-mu)
            float dd = xv[k] - mu[k];
            var[k] = fmaf(ETA_V_F, dd * dd, CV_F * var[k]);         // 0.98*var + 0.02*dd^2
            nv[k] = dd * rsqrtf(var[k]);                            // (x-mu)/sqrt(var)
        }
        norm[t * (D_DIM / 4) + d4]                    = make_float4(nv[0], nv[1], nv[2], nv[3]);
        info[t * (2 * D_DIM / 4) + d4]                = make_float4(mu[0], mu[1], mu[2], mu[3]);
        info[t * (2 * D_DIM / 4) + (D_DIM / 4) + d4]  = make_float4(var[0], var[1], var[2], var[3]);
    }
}

extern "C" void kernel_launch(void* const* d_in, const int* in_sizes, int n_in,
                              void* d_out, int out_size) {
    const float4* x4 = (const float4*)d_in[0];
    float4* out4 = (float4*)d_out;

    dim3 b(128);
    dim3 g1((D_DIM / 4) / 128, C_CHUNKS);   // (2, 256)
    p1_kernel<<<g1, b>>>(x4);
    p2_kernel<<<D_DIM / 256, dim3(256)>>>();
    p5_kernel<<<g1, b>>>(x4, out4);
}